// round 3
// baseline (speedup 1.0000x reference)
#include <cuda_runtime.h>
#include <cuda_bf16.h>

#define N_NODES 50000
#define N_PAIRS 800000
#define N_EDGES2 1600000   // directed edges (both directions)
#define CIN 64
#define HLD 128

// ---------------- scratch (device globals; no allocations) ----------------
__device__ float  g_A[N_NODES * HLD];      // x @ W0_top
__device__ float  g_B[N_NODES * HLD];      // x @ W0_bot + b0
__device__ float4 g_aggH4[N_NODES * 32];   // per-node sum of hidden vectors (128 f32)
__device__ int    g_deg[N_NODES];
__device__ float  g_x1[N_NODES * CIN];
__device__ float  g_x2[N_NODES * CIN];
__device__ float  g_fe1t[N_PAIRS * 3];     // folded edge_conv1 contribution to final out
__device__ float  g_G[HLD * 3];            // ec1_W1 @ ec1_Wl_top @ ec2_Wl_mid
__device__ float  g_c3[3], g_va[3], g_vg[3];
__device__ float  g_W13[HLD * 3];          // ec2_W1 @ ec2_Wl_top
__device__ float  g_cc3[3];                // (ec2_b1 @ ec2_Wl_top) + ec2_bl
__device__ double g_sl[2];

__device__ __forceinline__ float lrelu(float v) { return v > 0.f ? v : 0.01f * v; }

// ---------------- weight folding (tiny, 1 block) ----------------
__global__ void k_fold(const float* __restrict__ e1W1, const float* __restrict__ e1Wl,
                       const float* __restrict__ e1b1, const float* __restrict__ e1bl,
                       const float* __restrict__ e2W1, const float* __restrict__ e2b1,
                       const float* __restrict__ e2Wl, const float* __restrict__ e2bl) {
    __shared__ float T[HLD * 3];
    __shared__ float u[HLD];
    int t = threadIdx.x;  // 128 threads
    // T[j][c] = sum_j' e1Wl[j][j'] * e2Wl[3+j'][c]
    float t0 = 0.f, t1 = 0.f, t2 = 0.f, uu = 0.f;
    for (int j = 0; j < HLD; j++) {
        float w = e1Wl[t * HLD + j];
        t0 += w * e2Wl[(3 + j) * 3 + 0];
        t1 += w * e2Wl[(3 + j) * 3 + 1];
        t2 += w * e2Wl[(3 + j) * 3 + 2];
        uu += e1b1[j] * e1Wl[j * HLD + t];
    }
    T[t * 3 + 0] = t0; T[t * 3 + 1] = t1; T[t * 3 + 2] = t2;
    u[t] = uu + e1bl[t];
    __syncthreads();
    // G[t][c] = sum_j e1W1[t][j] * T[j][c]
    float a0 = 0.f, a1 = 0.f, a2 = 0.f;
    for (int j = 0; j < HLD; j++) {
        float w = e1W1[t * HLD + j];
        a0 += w * T[j * 3 + 0];
        a1 += w * T[j * 3 + 1];
        a2 += w * T[j * 3 + 2];
    }
    g_G[t * 3 + 0] = a0; g_G[t * 3 + 1] = a1; g_G[t * 3 + 2] = a2;
    // W13[t][c] = sum_c' e2W1[t][c'] * e2Wl[c'][c]
    for (int c = 0; c < 3; c++) {
        float s = 0.f;
        for (int cp = 0; cp < 3; cp++) s += e2W1[t * 3 + cp] * e2Wl[cp * 3 + c];
        g_W13[t * 3 + c] = s;
    }
    if (t < 3) {
        float c3 = 0.f, va = 0.f, vg = 0.f;
        for (int j = 0; j < HLD; j++) {
            float w2 = e2Wl[(3 + j) * 3 + t];
            c3 += u[j] * w2;
            va += e1Wl[128 * HLD + j] * w2;   // actions row
            vg += e1Wl[129 * HLD + j] * w2;   // angles row
        }
        g_c3[t] = c3; g_va[t] = va; g_vg[t] = vg;
        float cc = e2bl[t];
        for (int cp = 0; cp < 3; cp++) cc += e2b1[cp] * e2Wl[cp * 3 + t];
        g_cc3[t] = cc;
    }
}

// ---------------- zero kernels ----------------
__global__ void k_zero_aggH() {
    int i = blockIdx.x * blockDim.x + threadIdx.x;
    int n = N_NODES * 32;
    float4 z = make_float4(0.f, 0.f, 0.f, 0.f);
    for (; i < n; i += gridDim.x * blockDim.x) g_aggH4[i] = z;
}
__global__ void k_zero_misc() {
    int i = blockIdx.x * blockDim.x + threadIdx.x;
    if (i < N_NODES) g_deg[i] = 0;
    if (i < 2) g_sl[i] = 0.0;
}
__global__ void k_deg(const int* __restrict__ dst) {
    int i = blockIdx.x * blockDim.x + threadIdx.x;
    if (i < N_EDGES2) atomicAdd(&g_deg[dst[i]], 1);
}

// ---------------- per-node pre-GEMM: A = x@W0_top, B = x@W0_bot + b0 ----------------
#define NT 32
__global__ __launch_bounds__(256) void k_pregemm(const float* __restrict__ x_ext, int sel,
                                                 const float* __restrict__ W0,
                                                 const float* __restrict__ b0) {
    const float* x = (sel == 0) ? x_ext : (sel == 1 ? g_x1 : g_x2);
    __shared__ float xs[NT * CIN];
    int base = blockIdx.x * NT;
    int t = threadIdx.x;
    const float4* x4 = (const float4*)x;
    float4* xs4 = (float4*)xs;
    for (int i = t; i < NT * (CIN / 4); i += 256) {
        int p = i >> 4, q = i & 15;
        int n = base + p;
        xs4[i] = (n < N_NODES) ? x4[n * 16 + q] : make_float4(0.f, 0.f, 0.f, 0.f);
    }
    __syncthreads();
    int col = t & 127;
    int row_off = (t < 128) ? 0 : 64;
    float acc[NT];
#pragma unroll
    for (int p = 0; p < NT; p++) acc[p] = 0.f;
    for (int kt = 0; kt < 16; kt++) {
        float w0 = W0[(row_off + kt * 4 + 0) * HLD + col];
        float w1 = W0[(row_off + kt * 4 + 1) * HLD + col];
        float w2 = W0[(row_off + kt * 4 + 2) * HLD + col];
        float w3 = W0[(row_off + kt * 4 + 3) * HLD + col];
#pragma unroll
        for (int p = 0; p < NT; p++) {
            float4 xv = xs4[p * 16 + kt];
            acc[p] = fmaf(xv.x, w0, acc[p]);
            acc[p] = fmaf(xv.y, w1, acc[p]);
            acc[p] = fmaf(xv.z, w2, acc[p]);
            acc[p] = fmaf(xv.w, w3, acc[p]);
        }
    }
    float bb = (t >= 128) ? b0[col] : 0.f;
    float* out = (t < 128) ? g_A : g_B;
    for (int p = 0; p < NT; p++) {
        int n = base + p;
        if (n < N_NODES) out[n * HLD + col] = acc[p] + bb;
    }
}

// ---------------- scatter hidden vectors: aggH[d] += lrelu(A[s]+B[d]) ----------------
// 256 threads = 8 warps; each warp handles 8 consecutive edges; lane owns one float4.
#define SE 64
__global__ __launch_bounds__(256) void k_scatterH(const int* __restrict__ src,
                                                  const int* __restrict__ dst) {
    int t = threadIdx.x;
    int warp = t >> 5, lane = t & 31;
    const float4* A4 = (const float4*)g_A;
    const float4* B4 = (const float4*)g_B;
    int ebase = blockIdx.x * SE + warp * 8;
#pragma unroll
    for (int i = 0; i < 8; i++) {
        int e = ebase + i;
        if (e < N_EDGES2) {
            int s = src[e], d = dst[e];
            float4 a = A4[s * 32 + lane];
            float4 b = B4[d * 32 + lane];
            float4 h;
            h.x = lrelu(a.x + b.x);
            h.y = lrelu(a.y + b.y);
            h.z = lrelu(a.z + b.z);
            h.w = lrelu(a.w + b.w);
            float4* p = &g_aggH4[d * 32 + lane];
            asm volatile("red.global.add.v4.f32 [%0], {%1,%2,%3,%4};"
                         :: "l"(p), "f"(h.x), "f"(h.y), "f"(h.z), "f"(h.w)
                         : "memory");
        }
    }
}

// ---------------- node GEMM: x_out = deg>0 ? (aggH @ W1)/deg + b1 : 0 ----------------
__global__ __launch_bounds__(256) void k_nodegemm(const float* __restrict__ W1,  // 128x64
                                                  const float* __restrict__ b1, int sel) {
    __shared__ float hs[NT * 132];
    int base = blockIdx.x * NT;
    int t = threadIdx.x;
    float4* hs4 = (float4*)hs;
    for (int i = t; i < NT * 32; i += 256) {
        int p = i >> 5, q = i & 31;
        int n = base + p;
        hs4[p * 33 + q] = (n < N_NODES) ? g_aggH4[n * 32 + q] : make_float4(0.f, 0.f, 0.f, 0.f);
    }
    __syncthreads();
    int p = t >> 3;
    int cb = (t & 7) * 8;
    float acc[8];
#pragma unroll
    for (int j = 0; j < 8; j++) acc[j] = 0.f;
    const float* hrow = hs + p * 132;
#pragma unroll 4
    for (int k = 0; k < HLD; k++) {
        float hk = hrow[k];
        float4 w0 = *(const float4*)(W1 + k * 64 + cb);
        float4 w1 = *(const float4*)(W1 + k * 64 + cb + 4);
        acc[0] = fmaf(hk, w0.x, acc[0]);
        acc[1] = fmaf(hk, w0.y, acc[1]);
        acc[2] = fmaf(hk, w0.z, acc[2]);
        acc[3] = fmaf(hk, w0.w, acc[3]);
        acc[4] = fmaf(hk, w1.x, acc[4]);
        acc[5] = fmaf(hk, w1.y, acc[5]);
        acc[6] = fmaf(hk, w1.z, acc[6]);
        acc[7] = fmaf(hk, w1.w, acc[7]);
    }
    int n = base + p;
    if (n < N_NODES) {
        int d = g_deg[n];
        float inv = (d > 0) ? (1.f / (float)d) : 0.f;
        float* out = (sel == 1) ? g_x1 : g_x2;
#pragma unroll
        for (int j = 0; j < 8; j++)
            out[n * 64 + cb + j] = (d > 0) ? (acc[j] * inv + b1[cb + j]) : 0.f;
    }
}

// ---------------- edge_conv1 pair kernel: side-loss + folded fe term ----------------
#define ET 32
__global__ __launch_bounds__(256) void k_pair1(const int* __restrict__ src,
                                               const int* __restrict__ dst,
                                               const float* __restrict__ actions,
                                               const float* __restrict__ angles,
                                               const float* __restrict__ W1) {  // 128x128 (ec1_W1)
    __shared__ float hsum[ET * 132];
    __shared__ float hdif[ET * 132];
    __shared__ int s_src[ET], s_dst[ET];
    __shared__ float warp_part[8];
    int base = blockIdx.x * ET;
    int t = threadIdx.x;
    if (t < ET) { int e = base + t; s_src[t] = (e < N_PAIRS) ? src[e] : -1; }
    else if (t < 2 * ET) { int e = base + t - ET; s_dst[t - ET] = (e < N_PAIRS) ? dst[e] : -1; }
    __syncthreads();
    const float4* A4 = (const float4*)g_A;
    const float4* B4 = (const float4*)g_B;
    for (int i = t; i < ET * 32; i += 256) {
        int p = i >> 5, q = i & 31;
        float4 hsv = make_float4(0.f, 0.f, 0.f, 0.f);
        float4 hdv = hsv;
        int s = s_src[p];
        if (s >= 0) {
            int d = s_dst[p];
            float4 as4 = A4[s * 32 + q], bd4 = B4[d * 32 + q];
            float4 ad4 = A4[d * 32 + q], bs4 = B4[s * 32 + q];
            float h1x = lrelu(as4.x + bd4.x), h2x = lrelu(ad4.x + bs4.x);
            float h1y = lrelu(as4.y + bd4.y), h2y = lrelu(ad4.y + bs4.y);
            float h1z = lrelu(as4.z + bd4.z), h2z = lrelu(ad4.z + bs4.z);
            float h1w = lrelu(as4.w + bd4.w), h2w = lrelu(ad4.w + bs4.w);
            hsv = make_float4(0.5f * (h1x + h2x), 0.5f * (h1y + h2y),
                              0.5f * (h1z + h2z), 0.5f * (h1w + h2w));
            hdv = make_float4(h1x - h2x, h1y - h2y, h1z - h2z, h1w - h2w);
        }
        ((float4*)hsum)[p * 33 + q] = hsv;
        ((float4*)hdif)[p * 33 + q] = hdv;
    }
    __syncthreads();
    // main: (hdif tile 32x128) @ W1 (128x128) -> square-accumulate into loss
    int p = t >> 3;
    int cb = (t & 7) * 16;
    float acc[16];
#pragma unroll
    for (int j = 0; j < 16; j++) acc[j] = 0.f;
    const float* hrow = hdif + p * 132;
#pragma unroll 2
    for (int k = 0; k < HLD; k++) {
        float hk = hrow[k];
        const float* wr = W1 + k * HLD + cb;
        float4 w0 = *(const float4*)(wr);
        float4 w1 = *(const float4*)(wr + 4);
        float4 w2 = *(const float4*)(wr + 8);
        float4 w3 = *(const float4*)(wr + 12);
        acc[0]  = fmaf(hk, w0.x, acc[0]);  acc[1]  = fmaf(hk, w0.y, acc[1]);
        acc[2]  = fmaf(hk, w0.z, acc[2]);  acc[3]  = fmaf(hk, w0.w, acc[3]);
        acc[4]  = fmaf(hk, w1.x, acc[4]);  acc[5]  = fmaf(hk, w1.y, acc[5]);
        acc[6]  = fmaf(hk, w1.z, acc[6]);  acc[7]  = fmaf(hk, w1.w, acc[7]);
        acc[8]  = fmaf(hk, w2.x, acc[8]);  acc[9]  = fmaf(hk, w2.y, acc[9]);
        acc[10] = fmaf(hk, w2.z, acc[10]); acc[11] = fmaf(hk, w2.w, acc[11]);
        acc[12] = fmaf(hk, w3.x, acc[12]); acc[13] = fmaf(hk, w3.y, acc[13]);
        acc[14] = fmaf(hk, w3.z, acc[14]); acc[15] = fmaf(hk, w3.w, acc[15]);
    }
    float lsum = 0.f;
#pragma unroll
    for (int j = 0; j < 16; j++) lsum = fmaf(acc[j], acc[j], lsum);
    // folded fe1 term: hs @ G + c3 + act*va + ang*vg
    if (t < 96) {
        int p2 = t / 3, c = t - p2 * 3;
        int e = base + p2;
        if (s_src[p2] >= 0) {
            const float* hr = hsum + p2 * 132;
            float s = 0.f;
            for (int k = 0; k < HLD; k++) s = fmaf(hr[k], g_G[k * 3 + c], s);
            g_fe1t[e * 3 + c] = s + g_c3[c] + actions[e] * g_va[c] + angles[e] * g_vg[c];
        }
    }
    // loss reduction
    for (int off = 16; off; off >>= 1) lsum += __shfl_down_sync(0xffffffffu, lsum, off);
    if ((t & 31) == 0) warp_part[t >> 5] = lsum;
    __syncthreads();
    if (t == 0) {
        double s = 0.0;
        for (int j = 0; j < 8; j++) s += (double)warp_part[j];
        atomicAdd(&g_sl[0], s);
    }
}

// ---------------- edge_conv2 pair kernel: final output ----------------
__global__ __launch_bounds__(256) void k_pair2(const int* __restrict__ src,
                                               const int* __restrict__ dst,
                                               const float* __restrict__ Wd,  // ec2_W1 128x3
                                               float* __restrict__ out) {
    __shared__ float sW13[HLD * 4];
    __shared__ float sWd[HLD * 4];
    __shared__ float warp_loss[8];
    int t = threadIdx.x;
    if (t < HLD) {
        for (int c = 0; c < 3; c++) {
            sW13[t * 4 + c] = g_W13[t * 3 + c];
            sWd[t * 4 + c] = Wd[t * 3 + c];
        }
    }
    __syncthreads();
    int gw = blockIdx.x * 8 + (t >> 5);
    int lane = t & 31;
    float lloss = 0.f;
    if (gw < N_PAIRS) {
        int s = src[gw], d = dst[gw];
        const float4* A4 = (const float4*)g_A;
        const float4* B4 = (const float4*)g_B;
        float4 as4 = A4[s * 32 + lane], bd4 = B4[d * 32 + lane];
        float4 ad4 = A4[d * 32 + lane], bs4 = B4[s * 32 + lane];
        float h1[4], h2[4];
        h1[0] = lrelu(as4.x + bd4.x); h2[0] = lrelu(ad4.x + bs4.x);
        h1[1] = lrelu(as4.y + bd4.y); h2[1] = lrelu(ad4.y + bs4.y);
        h1[2] = lrelu(as4.z + bd4.z); h2[2] = lrelu(ad4.z + bs4.z);
        h1[3] = lrelu(as4.w + bd4.w); h2[3] = lrelu(ad4.w + bs4.w);
        float ms0 = 0.f, ms1 = 0.f, ms2 = 0.f, md0 = 0.f, md1 = 0.f, md2 = 0.f;
#pragma unroll
        for (int j = 0; j < 4; j++) {
            int k = lane * 4 + j;
            float hv = h1[j] + h2[j], dv = h1[j] - h2[j];
            ms0 = fmaf(hv, sW13[k * 4 + 0], ms0);
            ms1 = fmaf(hv, sW13[k * 4 + 1], ms1);
            ms2 = fmaf(hv, sW13[k * 4 + 2], ms2);
            md0 = fmaf(dv, sWd[k * 4 + 0], md0);
            md1 = fmaf(dv, sWd[k * 4 + 1], md1);
            md2 = fmaf(dv, sWd[k * 4 + 2], md2);
        }
        for (int off = 16; off; off >>= 1) {
            unsigned m = 0xffffffffu;
            ms0 += __shfl_down_sync(m, ms0, off);
            ms1 += __shfl_down_sync(m, ms1, off);
            ms2 += __shfl_down_sync(m, ms2, off);
            md0 += __shfl_down_sync(m, md0, off);
            md1 += __shfl_down_sync(m, md1, off);
            md2 += __shfl_down_sync(m, md2, off);
        }
        if (lane == 0) {
            out[gw * 3 + 0] = 0.5f * ms0 + g_cc3[0] + g_fe1t[gw * 3 + 0];
            out[gw * 3 + 1] = 0.5f * ms1 + g_cc3[1] + g_fe1t[gw * 3 + 1];
            out[gw * 3 + 2] = 0.5f * ms2 + g_cc3[2] + g_fe1t[gw * 3 + 2];
            lloss = md0 * md0 + md1 * md1 + md2 * md2;
        }
    }
    if (lane == 0) warp_loss[t >> 5] = lloss;
    __syncthreads();
    if (t == 0) {
        double s = 0.0;
        for (int j = 0; j < 8; j++) s += (double)warp_loss[j];
        atomicAdd(&g_sl[1], s);
    }
}

__global__ void k_final(float* out, int out_size) {
    out[out_size - 1] =
        (float)(0.5 * (g_sl[0] / ((double)N_PAIRS * 128.0) + g_sl[1] / ((double)N_PAIRS * 3.0)));
}

// ---------------- launch ----------------
extern "C" void kernel_launch(void* const* d_in, const int* in_sizes, int n_in,
                              void* d_out, int out_size) {
    const float* x0      = (const float*)d_in[0];
    const int*   ei      = (const int*)d_in[1];
    const float* angles  = (const float*)d_in[2];
    const float* actions = (const float*)d_in[3];
    const float* nc1_W0 = (const float*)d_in[5];
    const float* nc1_b0 = (const float*)d_in[6];
    const float* nc1_W1 = (const float*)d_in[7];
    const float* nc1_b1 = (const float*)d_in[8];
    const float* ec1_W0 = (const float*)d_in[9];
    const float* ec1_b0 = (const float*)d_in[10];
    const float* ec1_W1 = (const float*)d_in[11];
    const float* ec1_b1 = (const float*)d_in[12];
    const float* ec1_Wl = (const float*)d_in[13];
    const float* ec1_bl = (const float*)d_in[14];
    const float* nc2_W0 = (const float*)d_in[15];
    const float* nc2_b0 = (const float*)d_in[16];
    const float* nc2_W1 = (const float*)d_in[17];
    const float* nc2_b1 = (const float*)d_in[18];
    const float* ec2_W0 = (const float*)d_in[19];
    const float* ec2_b0 = (const float*)d_in[20];
    const float* ec2_W1 = (const float*)d_in[21];
    const float* ec2_b1 = (const float*)d_in[22];
    const float* ec2_Wl = (const float*)d_in[23];
    const float* ec2_bl = (const float*)d_in[24];
    float* out = (float*)d_out;

    const int* src = ei;
    const int* dst = ei + N_EDGES2;

    int nb_pre   = (N_NODES + NT - 1) / NT;        // 1563
    int nb_scat  = (N_EDGES2 + SE - 1) / SE;       // 25000
    int nb_pair1 = (N_PAIRS + ET - 1) / ET;        // 25000
    int nb_pair2 = (N_PAIRS + 7) / 8;              // 100000
    int nb_deg   = (N_EDGES2 + 255) / 256;

    k_fold<<<1, 128>>>(ec1_W1, ec1_Wl, ec1_b1, ec1_bl, ec2_W1, ec2_b1, ec2_Wl, ec2_bl);
    k_zero_aggH<<<2048, 256>>>();
    k_zero_misc<<<(N_NODES + 255) / 256, 256>>>();
    k_deg<<<nb_deg, 256>>>(dst);

    // node_conv 1: h-sum scatter, then single node-level GEMM
    k_pregemm<<<nb_pre, 256>>>(x0, 0, nc1_W0, nc1_b0);
    k_scatterH<<<nb_scat, 256>>>(src, dst);
    k_nodegemm<<<nb_pre, 256>>>(nc1_W1, nc1_b1, 1);

    // edge_conv 1 (folded)
    k_pregemm<<<nb_pre, 256>>>(nullptr, 1, ec1_W0, ec1_b0);
    k_pair1<<<nb_pair1, 256>>>(src, dst, actions, angles, ec1_W1);

    // node_conv 2
    k_zero_aggH<<<2048, 256>>>();
    k_pregemm<<<nb_pre, 256>>>(nullptr, 1, nc2_W0, nc2_b0);
    k_scatterH<<<nb_scat, 256>>>(src, dst);
    k_nodegemm<<<nb_pre, 256>>>(nc2_W1, nc2_b1, 2);

    // edge_conv 2 -> final output
    k_pregemm<<<nb_pre, 256>>>(nullptr, 2, ec2_W0, ec2_b0);
    k_pair2<<<nb_pair2, 256>>>(src, dst, ec2_W1, out);
    k_final<<<1, 1>>>(out, out_size);
}

// round 9
// speedup vs baseline: 1.0701x; 1.0701x over previous
#include <cuda_runtime.h>
#include <cuda_bf16.h>

#define N_NODES 50000
#define N_PAIRS 800000
#define N_EDGES2 1600000   // directed edges (both directions)
#define CIN 64
#define HLD 128
#define SCAN_B ((N_NODES + 255) / 256)   // 196

// ---------------- scratch (device globals; no allocations) ----------------
__device__ float  g_A[N_NODES * HLD];      // x @ W0_top
__device__ float  g_B[N_NODES * HLD];      // x @ W0_bot + b0
__device__ float4 g_aggH4[N_NODES * 32];   // per-node sum of hidden vectors (128 f32)
__device__ int    g_deg[N_NODES];
__device__ int    g_off[N_NODES + 1];      // CSR row offsets (by dst)
__device__ int    g_fill[N_NODES];         // atomic cursors
__device__ int    g_part[256];             // scan partials
__device__ int    g_partoff[256];
__device__ int    g_eid[N_EDGES2];         // CSR: src node of each in-edge
__device__ float  g_x1[N_NODES * CIN];
__device__ float  g_x2[N_NODES * CIN];
__device__ float  g_fe1t[N_PAIRS * 3];     // folded edge_conv1 contribution to final out
__device__ float  g_G[HLD * 3];            // ec1_W1 @ ec1_Wl_top @ ec2_Wl_mid
__device__ float  g_c3[3], g_va[3], g_vg[3];
__device__ float  g_W13[HLD * 3];          // ec2_W1 @ ec2_Wl_top
__device__ float  g_cc3[3];                // (ec2_b1 @ ec2_Wl_top) + ec2_bl
__device__ double g_sl[2];

__device__ __forceinline__ float lrelu(float v) { return v > 0.f ? v : 0.01f * v; }
__device__ __forceinline__ float4 lrelu4(float4 a, float4 b) {
    float4 r;
    r.x = lrelu(a.x + b.x);
    r.y = lrelu(a.y + b.y);
    r.z = lrelu(a.z + b.z);
    r.w = lrelu(a.w + b.w);
    return r;
}

// ---------------- weight folding (tiny, 1 block) ----------------
__global__ void k_fold(const float* __restrict__ e1W1, const float* __restrict__ e1Wl,
                       const float* __restrict__ e1b1, const float* __restrict__ e1bl,
                       const float* __restrict__ e2W1, const float* __restrict__ e2b1,
                       const float* __restrict__ e2Wl, const float* __restrict__ e2bl) {
    __shared__ float T[HLD * 3];
    __shared__ float u[HLD];
    int t = threadIdx.x;  // 128 threads
    float t0 = 0.f, t1 = 0.f, t2 = 0.f, uu = 0.f;
    for (int j = 0; j < HLD; j++) {
        float w = e1Wl[t * HLD + j];
        t0 += w * e2Wl[(3 + j) * 3 + 0];
        t1 += w * e2Wl[(3 + j) * 3 + 1];
        t2 += w * e2Wl[(3 + j) * 3 + 2];
        uu += e1b1[j] * e1Wl[j * HLD + t];
    }
    T[t * 3 + 0] = t0; T[t * 3 + 1] = t1; T[t * 3 + 2] = t2;
    u[t] = uu + e1bl[t];
    __syncthreads();
    float a0 = 0.f, a1 = 0.f, a2 = 0.f;
    for (int j = 0; j < HLD; j++) {
        float w = e1W1[t * HLD + j];
        a0 += w * T[j * 3 + 0];
        a1 += w * T[j * 3 + 1];
        a2 += w * T[j * 3 + 2];
    }
    g_G[t * 3 + 0] = a0; g_G[t * 3 + 1] = a1; g_G[t * 3 + 2] = a2;
    for (int c = 0; c < 3; c++) {
        float s = 0.f;
        for (int cp = 0; cp < 3; cp++) s += e2W1[t * 3 + cp] * e2Wl[cp * 3 + c];
        g_W13[t * 3 + c] = s;
    }
    if (t < 3) {
        float c3 = 0.f, va = 0.f, vg = 0.f;
        for (int j = 0; j < HLD; j++) {
            float w2 = e2Wl[(3 + j) * 3 + t];
            c3 += u[j] * w2;
            va += e1Wl[128 * HLD + j] * w2;   // actions row
            vg += e1Wl[129 * HLD + j] * w2;   // angles row
        }
        g_c3[t] = c3; g_va[t] = va; g_vg[t] = vg;
        float cc = e2bl[t];
        for (int cp = 0; cp < 3; cp++) cc += e2b1[cp] * e2Wl[cp * 3 + t];
        g_cc3[t] = cc;
    }
}

// ---------------- CSR build ----------------
__global__ void k_zero_misc() {
    int i = blockIdx.x * blockDim.x + threadIdx.x;
    if (i < N_NODES) g_deg[i] = 0;
    if (i < 2) g_sl[i] = 0.0;
}
__global__ void k_deg(const int* __restrict__ dst) {
    int i = blockIdx.x * blockDim.x + threadIdx.x;
    if (i < N_EDGES2) atomicAdd(&g_deg[dst[i]], 1);
}
__global__ void k_scan_part() {
    __shared__ int sh[256];
    int t = threadIdx.x;
    int i = blockIdx.x * 256 + t;
    int v = (i < N_NODES) ? g_deg[i] : 0;
    sh[t] = v;
    __syncthreads();
    for (int o = 1; o < 256; o <<= 1) {
        int x = (t >= o) ? sh[t - o] : 0;
        __syncthreads();
        sh[t] += x;
        __syncthreads();
    }
    if (i < N_NODES) g_off[i] = sh[t] - v;   // exclusive within block
    if (t == 255) g_part[blockIdx.x] = sh[255];
}
__global__ void k_scan_tot() {
    __shared__ int sh[256];
    int t = threadIdx.x;
    int v = (t < SCAN_B) ? g_part[t] : 0;
    sh[t] = v;
    __syncthreads();
    for (int o = 1; o < 256; o <<= 1) {
        int x = (t >= o) ? sh[t - o] : 0;
        __syncthreads();
        sh[t] += x;
        __syncthreads();
    }
    g_partoff[t] = sh[t] - v;
}
__global__ void k_scan_add() {
    int i = blockIdx.x * blockDim.x + threadIdx.x;
    if (i < N_NODES) {
        int off = g_off[i] + g_partoff[i >> 8];
        g_off[i] = off;
        g_fill[i] = off;
    }
    if (i == 0) g_off[N_NODES] = N_EDGES2;
}
__global__ void k_csr(const int* __restrict__ src, const int* __restrict__ dst) {
    int i = blockIdx.x * blockDim.x + threadIdx.x;
    if (i < N_EDGES2) {
        int d = dst[i];
        int pos = atomicAdd(&g_fill[d], 1);
        g_eid[pos] = src[i];
    }
}

// ---------------- per-node pre-GEMM: A = x@W0_top, B = x@W0_bot + b0 ----------------
#define NT 32
__global__ __launch_bounds__(256) void k_pregemm(const float* __restrict__ x_ext, int sel,
                                                 const float* __restrict__ W0,
                                                 const float* __restrict__ b0) {
    const float* x = (sel == 0) ? x_ext : (sel == 1 ? g_x1 : g_x2);
    __shared__ float xs[NT * CIN];
    int base = blockIdx.x * NT;
    int t = threadIdx.x;
    const float4* x4 = (const float4*)x;
    float4* xs4 = (float4*)xs;
    for (int i = t; i < NT * (CIN / 4); i += 256) {
        int p = i >> 4, q = i & 15;
        int n = base + p;
        xs4[i] = (n < N_NODES) ? x4[n * 16 + q] : make_float4(0.f, 0.f, 0.f, 0.f);
    }
    __syncthreads();
    int col = t & 127;
    int row_off = (t < 128) ? 0 : 64;
    float acc[NT];
#pragma unroll
    for (int p = 0; p < NT; p++) acc[p] = 0.f;
    for (int kt = 0; kt < 16; kt++) {
        float w0 = W0[(row_off + kt * 4 + 0) * HLD + col];
        float w1 = W0[(row_off + kt * 4 + 1) * HLD + col];
        float w2 = W0[(row_off + kt * 4 + 2) * HLD + col];
        float w3 = W0[(row_off + kt * 4 + 3) * HLD + col];
#pragma unroll
        for (int p = 0; p < NT; p++) {
            float4 xv = xs4[p * 16 + kt];
            acc[p] = fmaf(xv.x, w0, acc[p]);
            acc[p] = fmaf(xv.y, w1, acc[p]);
            acc[p] = fmaf(xv.z, w2, acc[p]);
            acc[p] = fmaf(xv.w, w3, acc[p]);
        }
    }
    float bb = (t >= 128) ? b0[col] : 0.f;
    float* out = (t < 128) ? g_A : g_B;
    for (int p = 0; p < NT; p++) {
        int n = base + p;
        if (n < N_NODES) out[n * HLD + col] = acc[p] + bb;
    }
}

// ---------------- gather hidden-vector sums via CSR (NO float atomics) ----------------
// One warp per node; lane owns one float4 column slice of the 128-dim hidden.
__global__ __launch_bounds__(256) void k_gatherH() {
    int t = threadIdx.x;
    int warp = t >> 5, lane = t & 31;
    int n = blockIdx.x * 8 + warp;
    if (n >= N_NODES) return;
    const float4* A4 = (const float4*)g_A;
    const float4* B4 = (const float4*)g_B;
    int off = g_off[n];
    int len = g_off[n + 1] - off;
    float4 b = B4[n * 32 + lane];
    float4 acc = make_float4(0.f, 0.f, 0.f, 0.f);
    int i = 0;
    for (; i + 4 <= len; i += 4) {
        int s0 = g_eid[off + i + 0];
        int s1 = g_eid[off + i + 1];
        int s2 = g_eid[off + i + 2];
        int s3 = g_eid[off + i + 3];
        float4 a0 = A4[s0 * 32 + lane];
        float4 a1 = A4[s1 * 32 + lane];
        float4 a2 = A4[s2 * 32 + lane];
        float4 a3 = A4[s3 * 32 + lane];
        float4 h0 = lrelu4(a0, b), h1 = lrelu4(a1, b);
        float4 h2 = lrelu4(a2, b), h3 = lrelu4(a3, b);
        acc.x += (h0.x + h1.x) + (h2.x + h3.x);
        acc.y += (h0.y + h1.y) + (h2.y + h3.y);
        acc.z += (h0.z + h1.z) + (h2.z + h3.z);
        acc.w += (h0.w + h1.w) + (h2.w + h3.w);
    }
    for (; i < len; i++) {
        int s = g_eid[off + i];
        float4 h = lrelu4(A4[s * 32 + lane], b);
        acc.x += h.x; acc.y += h.y; acc.z += h.z; acc.w += h.w;
    }
    g_aggH4[n * 32 + lane] = acc;
}

// ---------------- node GEMM: x_out = deg>0 ? (aggH @ W1)/deg + b1 : 0 ----------------
__global__ __launch_bounds__(256) void k_nodegemm(const float* __restrict__ W1,  // 128x64
                                                  const float* __restrict__ b1, int sel) {
    __shared__ float hs[NT * 132];
    int base = blockIdx.x * NT;
    int t = threadIdx.x;
    float4* hs4 = (float4*)hs;
    for (int i = t; i < NT * 32; i += 256) {
        int p = i >> 5, q = i & 31;
        int n = base + p;
        hs4[p * 33 + q] = (n < N_NODES) ? g_aggH4[n * 32 + q] : make_float4(0.f, 0.f, 0.f, 0.f);
    }
    __syncthreads();
    int p = t >> 3;
    int cb = (t & 7) * 8;
    float acc[8];
#pragma unroll
    for (int j = 0; j < 8; j++) acc[j] = 0.f;
    const float* hrow = hs + p * 132;
#pragma unroll 4
    for (int k = 0; k < HLD; k++) {
        float hk = hrow[k];
        float4 w0 = *(const float4*)(W1 + k * 64 + cb);
        float4 w1 = *(const float4*)(W1 + k * 64 + cb + 4);
        acc[0] = fmaf(hk, w0.x, acc[0]);
        acc[1] = fmaf(hk, w0.y, acc[1]);
        acc[2] = fmaf(hk, w0.z, acc[2]);
        acc[3] = fmaf(hk, w0.w, acc[3]);
        acc[4] = fmaf(hk, w1.x, acc[4]);
        acc[5] = fmaf(hk, w1.y, acc[5]);
        acc[6] = fmaf(hk, w1.z, acc[6]);
        acc[7] = fmaf(hk, w1.w, acc[7]);
    }
    int n = base + p;
    if (n < N_NODES) {
        int d = g_off[n + 1] - g_off[n];
        float inv = (d > 0) ? (1.f / (float)d) : 0.f;
        float* out = (sel == 1) ? g_x1 : g_x2;
#pragma unroll
        for (int j = 0; j < 8; j++)
            out[n * 64 + cb + j] = (d > 0) ? (acc[j] * inv + b1[cb + j]) : 0.f;
    }
}

// ---------------- edge_conv1 pair kernel: side-loss + folded fe term ----------------
#define ET 32
__global__ __launch_bounds__(256) void k_pair1(const int* __restrict__ src,
                                               const int* __restrict__ dst,
                                               const float* __restrict__ actions,
                                               const float* __restrict__ angles,
                                               const float* __restrict__ W1) {  // 128x128 (ec1_W1)
    __shared__ float hsum[ET * 132];
    __shared__ float hdif[ET * 132];
    __shared__ int s_src[ET], s_dst[ET];
    __shared__ float warp_part[8];
    int base = blockIdx.x * ET;
    int t = threadIdx.x;
    if (t < ET) { int e = base + t; s_src[t] = (e < N_PAIRS) ? src[e] : -1; }
    else if (t < 2 * ET) { int e = base + t - ET; s_dst[t - ET] = (e < N_PAIRS) ? dst[e] : -1; }
    __syncthreads();
    const float4* A4 = (const float4*)g_A;
    const float4* B4 = (const float4*)g_B;
    for (int i = t; i < ET * 32; i += 256) {
        int p = i >> 5, q = i & 31;
        float4 hsv = make_float4(0.f, 0.f, 0.f, 0.f);
        float4 hdv = hsv;
        int s = s_src[p];
        if (s >= 0) {
            int d = s_dst[p];
            float4 as4 = A4[s * 32 + q], bd4 = B4[d * 32 + q];
            float4 ad4 = A4[d * 32 + q], bs4 = B4[s * 32 + q];
            float h1x = lrelu(as4.x + bd4.x), h2x = lrelu(ad4.x + bs4.x);
            float h1y = lrelu(as4.y + bd4.y), h2y = lrelu(ad4.y + bs4.y);
            float h1z = lrelu(as4.z + bd4.z), h2z = lrelu(ad4.z + bs4.z);
            float h1w = lrelu(as4.w + bd4.w), h2w = lrelu(ad4.w + bs4.w);
            hsv = make_float4(0.5f * (h1x + h2x), 0.5f * (h1y + h2y),
                              0.5f * (h1z + h2z), 0.5f * (h1w + h2w));
            hdv = make_float4(h1x - h2x, h1y - h2y, h1z - h2z, h1w - h2w);
        }
        ((float4*)hsum)[p * 33 + q] = hsv;
        ((float4*)hdif)[p * 33 + q] = hdv;
    }
    __syncthreads();
    int p = t >> 3;
    int cb = (t & 7) * 16;
    float acc[16];
#pragma unroll
    for (int j = 0; j < 16; j++) acc[j] = 0.f;
    const float* hrow = hdif + p * 132;
#pragma unroll 2
    for (int k = 0; k < HLD; k++) {
        float hk = hrow[k];
        const float* wr = W1 + k * HLD + cb;
        float4 w0 = *(const float4*)(wr);
        float4 w1 = *(const float4*)(wr + 4);
        float4 w2 = *(const float4*)(wr + 8);
        float4 w3 = *(const float4*)(wr + 12);
        acc[0]  = fmaf(hk, w0.x, acc[0]);  acc[1]  = fmaf(hk, w0.y, acc[1]);
        acc[2]  = fmaf(hk, w0.z, acc[2]);  acc[3]  = fmaf(hk, w0.w, acc[3]);
        acc[4]  = fmaf(hk, w1.x, acc[4]);  acc[5]  = fmaf(hk, w1.y, acc[5]);
        acc[6]  = fmaf(hk, w1.z, acc[6]);  acc[7]  = fmaf(hk, w1.w, acc[7]);
        acc[8]  = fmaf(hk, w2.x, acc[8]);  acc[9]  = fmaf(hk, w2.y, acc[9]);
        acc[10] = fmaf(hk, w2.z, acc[10]); acc[11] = fmaf(hk, w2.w, acc[11]);
        acc[12] = fmaf(hk, w3.x, acc[12]); acc[13] = fmaf(hk, w3.y, acc[13]);
        acc[14] = fmaf(hk, w3.z, acc[14]); acc[15] = fmaf(hk, w3.w, acc[15]);
    }
    float lsum = 0.f;
#pragma unroll
    for (int j = 0; j < 16; j++) lsum = fmaf(acc[j], acc[j], lsum);
    if (t < 96) {
        int p2 = t / 3, c = t - p2 * 3;
        int e = base + p2;
        if (s_src[p2] >= 0) {
            const float* hr = hsum + p2 * 132;
            float s = 0.f;
            for (int k = 0; k < HLD; k++) s = fmaf(hr[k], g_G[k * 3 + c], s);
            g_fe1t[e * 3 + c] = s + g_c3[c] + actions[e] * g_va[c] + angles[e] * g_vg[c];
        }
    }
    for (int off = 16; off; off >>= 1) lsum += __shfl_down_sync(0xffffffffu, lsum, off);
    if ((t & 31) == 0) warp_part[t >> 5] = lsum;
    __syncthreads();
    if (t == 0) {
        double s = 0.0;
        for (int j = 0; j < 8; j++) s += (double)warp_part[j];
        atomicAdd(&g_sl[0], s);
    }
}

// ---------------- edge_conv2 pair kernel: final output (grid-stride) ----------------
#define P2_BLOCKS 2048
__global__ __launch_bounds__(256) void k_pair2(const int* __restrict__ src,
                                               const int* __restrict__ dst,
                                               const float* __restrict__ Wd,  // ec2_W1 128x3
                                               float* __restrict__ out) {
    __shared__ float sW13[HLD * 4];
    __shared__ float sWd[HLD * 4];
    __shared__ float warp_loss[8];
    int t = threadIdx.x;
    if (t < HLD) {
        for (int c = 0; c < 3; c++) {
            sW13[t * 4 + c] = g_W13[t * 3 + c];
            sWd[t * 4 + c] = Wd[t * 3 + c];
        }
    }
    __syncthreads();
    int warp = t >> 5, lane = t & 31;
    const float4* A4 = (const float4*)g_A;
    const float4* B4 = (const float4*)g_B;
    float lloss = 0.f;
    for (int gw = blockIdx.x * 8 + warp; gw < N_PAIRS; gw += P2_BLOCKS * 8) {
        int s = src[gw], d = dst[gw];
        float4 as4 = A4[s * 32 + lane], bd4 = B4[d * 32 + lane];
        float4 ad4 = A4[d * 32 + lane], bs4 = B4[s * 32 + lane];
        float h1[4], h2[4];
        h1[0] = lrelu(as4.x + bd4.x); h2[0] = lrelu(ad4.x + bs4.x);
        h1[1] = lrelu(as4.y + bd4.y); h2[1] = lrelu(ad4.y + bs4.y);
        h1[2] = lrelu(as4.z + bd4.z); h2[2] = lrelu(ad4.z + bs4.z);
        h1[3] = lrelu(as4.w + bd4.w); h2[3] = lrelu(ad4.w + bs4.w);
        float ms0 = 0.f, ms1 = 0.f, ms2 = 0.f, md0 = 0.f, md1 = 0.f, md2 = 0.f;
#pragma unroll
        for (int j = 0; j < 4; j++) {
            int k = lane * 4 + j;
            float hv = h1[j] + h2[j], dv = h1[j] - h2[j];
            ms0 = fmaf(hv, sW13[k * 4 + 0], ms0);
            ms1 = fmaf(hv, sW13[k * 4 + 1], ms1);
            ms2 = fmaf(hv, sW13[k * 4 + 2], ms2);
            md0 = fmaf(dv, sWd[k * 4 + 0], md0);
            md1 = fmaf(dv, sWd[k * 4 + 1], md1);
            md2 = fmaf(dv, sWd[k * 4 + 2], md2);
        }
        for (int off = 16; off; off >>= 1) {
            unsigned m = 0xffffffffu;
            ms0 += __shfl_down_sync(m, ms0, off);
            ms1 += __shfl_down_sync(m, ms1, off);
            ms2 += __shfl_down_sync(m, ms2, off);
            md0 += __shfl_down_sync(m, md0, off);
            md1 += __shfl_down_sync(m, md1, off);
            md2 += __shfl_down_sync(m, md2, off);
        }
        if (lane == 0) {
            out[gw * 3 + 0] = 0.5f * ms0 + g_cc3[0] + g_fe1t[gw * 3 + 0];
            out[gw * 3 + 1] = 0.5f * ms1 + g_cc3[1] + g_fe1t[gw * 3 + 1];
            out[gw * 3 + 2] = 0.5f * ms2 + g_cc3[2] + g_fe1t[gw * 3 + 2];
            lloss += md0 * md0 + md1 * md1 + md2 * md2;
        }
    }
    if (lane == 0) warp_loss[warp] = lloss;
    __syncthreads();
    if (t == 0) {
        double s = 0.0;
        for (int j = 0; j < 8; j++) s += (double)warp_loss[j];
        atomicAdd(&g_sl[1], s);
    }
}

__global__ void k_final(float* out, int out_size) {
    out[out_size - 1] =
        (float)(0.5 * (g_sl[0] / ((double)N_PAIRS * 128.0) + g_sl[1] / ((double)N_PAIRS * 3.0)));
}

// ---------------- launch ----------------
extern "C" void kernel_launch(void* const* d_in, const int* in_sizes, int n_in,
                              void* d_out, int out_size) {
    const float* x0      = (const float*)d_in[0];
    const int*   ei      = (const int*)d_in[1];
    const float* angles  = (const float*)d_in[2];
    const float* actions = (const float*)d_in[3];
    const float* nc1_W0 = (const float*)d_in[5];
    const float* nc1_b0 = (const float*)d_in[6];
    const float* nc1_W1 = (const float*)d_in[7];
    const float* nc1_b1 = (const float*)d_in[8];
    const float* ec1_W0 = (const float*)d_in[9];
    const float* ec1_b0 = (const float*)d_in[10];
    const float* ec1_W1 = (const float*)d_in[11];
    const float* ec1_b1 = (const float*)d_in[12];
    const float* ec1_Wl = (const float*)d_in[13];
    const float* ec1_bl = (const float*)d_in[14];
    const float* nc2_W0 = (const float*)d_in[15];
    const float* nc2_b0 = (const float*)d_in[16];
    const float* nc2_W1 = (const float*)d_in[17];
    const float* nc2_b1 = (const float*)d_in[18];
    const float* ec2_W0 = (const float*)d_in[19];
    const float* ec2_b0 = (const float*)d_in[20];
    const float* ec2_W1 = (const float*)d_in[21];
    const float* ec2_b1 = (const float*)d_in[22];
    const float* ec2_Wl = (const float*)d_in[23];
    const float* ec2_bl = (const float*)d_in[24];
    float* out = (float*)d_out;

    const int* src = ei;
    const int* dst = ei + N_EDGES2;

    int nb_pre   = (N_NODES + NT - 1) / NT;        // 1563
    int nb_gath  = (N_NODES + 7) / 8;              // 6250
    int nb_pair1 = (N_PAIRS + ET - 1) / ET;        // 25000
    int nb_e     = (N_EDGES2 + 255) / 256;         // 6250
    int nb_n     = (N_NODES + 255) / 256;          // 196

    // CSR build (by dst)
    k_zero_misc<<<nb_n, 256>>>();
    k_deg<<<nb_e, 256>>>(dst);
    k_scan_part<<<SCAN_B, 256>>>();
    k_scan_tot<<<1, 256>>>();
    k_scan_add<<<nb_n, 256>>>();
    k_csr<<<nb_e, 256>>>(src, dst);
    k_fold<<<1, 128>>>(ec1_W1, ec1_Wl, ec1_b1, ec1_bl, ec2_W1, ec2_b1, ec2_Wl, ec2_bl);

    // node_conv 1: gather hidden sums (no atomics), then node-level GEMM
    k_pregemm<<<nb_pre, 256>>>(x0, 0, nc1_W0, nc1_b0);
    k_gatherH<<<nb_gath, 256>>>();
    k_nodegemm<<<nb_pre, 256>>>(nc1_W1, nc1_b1, 1);

    // edge_conv 1 (folded)
    k_pregemm<<<nb_pre, 256>>>(nullptr, 1, ec1_W0, ec1_b0);
    k_pair1<<<nb_pair1, 256>>>(src, dst, actions, angles, ec1_W1);

    // node_conv 2
    k_pregemm<<<nb_pre, 256>>>(nullptr, 1, nc2_W0, nc2_b0);
    k_gatherH<<<nb_gath, 256>>>();
    k_nodegemm<<<nb_pre, 256>>>(nc2_W1, nc2_b1, 2);

    // edge_conv 2 -> final output
    k_pregemm<<<nb_pre, 256>>>(nullptr, 2, ec2_W0, ec2_b0);
    k_pair2<<<P2_BLOCKS, 256>>>(src, dst, ec2_W1, out);
    k_final<<<1, 1>>>(out, out_size);
}